// round 1
// baseline (speedup 1.0000x reference)
#include <cuda_runtime.h>

#define Nn 32
#define Cc 512
#define Hh 64
#define Ww 64
#define CBn 32          // bottleneck channels C/R
#define Sp (Hh*Ww)      // 4096 spatial per channel
#define EPSv 1e-5f

// Scratch (allocation-free rule: __device__ globals)
__device__ float g_attn[Nn * Sp];      // logits -> attn (in place)
__device__ float g_ctx[Nn * Cc];       // pooled context
__device__ float g_delta[Nn * Cc];     // per-(n,c) broadcast add term

// ---------------------------------------------------------------------------
// K1: logits[n,h,w] = sum_c x[n,c,h,w] * wk_w[c] + wk_b
// block = (n,h) row; 256 threads = 16 w-float4 groups x 16 c-chunks of 32
// ---------------------------------------------------------------------------
__global__ void k_logits(const float* __restrict__ x,
                         const float* __restrict__ wk_w,
                         const float* __restrict__ wk_b) {
    int n = blockIdx.x >> 6;          // / Hh
    int h = blockIdx.x & 63;          // % Hh
    int tid = threadIdx.x;            // 0..255
    int wq = tid & 15;                // float4 index over w (w = wq*4)
    int cc = tid >> 4;                // c-chunk 0..15 (32 channels each)

    const float4* xp = (const float4*)(x + (((size_t)(n * Cc + cc * 32)) * Hh + h) * Ww) + wq;
    const size_t cstride4 = Sp / 4;   // float4 stride between channels = 1024

    float4 acc = make_float4(0.f, 0.f, 0.f, 0.f);
#pragma unroll
    for (int i = 0; i < 32; i++) {
        float wv = __ldg(&wk_w[cc * 32 + i]);
        float4 v = __ldg(xp + (size_t)i * cstride4);
        acc.x += v.x * wv; acc.y += v.y * wv;
        acc.z += v.z * wv; acc.w += v.w * wv;
    }

    __shared__ float sred[16][Ww];
    sred[cc][wq * 4 + 0] = acc.x;
    sred[cc][wq * 4 + 1] = acc.y;
    sred[cc][wq * 4 + 2] = acc.z;
    sred[cc][wq * 4 + 3] = acc.w;
    __syncthreads();

    if (tid < Ww) {
        float s = 0.f;
#pragma unroll
        for (int k = 0; k < 16; k++) s += sred[k][tid];
        g_attn[((size_t)n * Hh + h) * Ww + tid] = s + __ldg(&wk_b[0]);
    }
}

// ---------------------------------------------------------------------------
// K2: softmax over H (axis=1) for each (n, w), in place on g_attn.
// block = n, 64 threads (one per w); column gather per thread, but rows are
// coalesced across the warp per h-iteration. Tiny kernel.
// ---------------------------------------------------------------------------
__global__ void k_softmax() {
    int n = blockIdx.x;
    int w = threadIdx.x;              // 0..63
    float* L = g_attn + (size_t)n * Sp;

    float vals[Hh];
    float m = -1e30f;
#pragma unroll
    for (int h = 0; h < Hh; h++) {
        vals[h] = L[h * Ww + w];
        m = fmaxf(m, vals[h]);
    }
    float sum = 0.f;
#pragma unroll
    for (int h = 0; h < Hh; h++) {
        vals[h] = __expf(vals[h] - m);
        sum += vals[h];
    }
    float inv = 1.f / sum;
#pragma unroll
    for (int h = 0; h < Hh; h++) L[h * Ww + w] = vals[h] * inv;
}

// ---------------------------------------------------------------------------
// K3: ctx[n,c] = sum_{h,w} x[n,c,h,w] * attn[n,h,w]
// block per (n,c); 128 threads reduce 4096 contiguous floats (float4).
// attn[n] (16 KB) is reused by 512 blocks -> L2 hits.
// ---------------------------------------------------------------------------
__global__ void k_ctx(const float* __restrict__ x) {
    int n = blockIdx.x >> 9;          // / Cc
    int c = blockIdx.x & 511;         // % Cc
    int tid = threadIdx.x;            // 0..127

    const float4* xp = (const float4*)(x + ((size_t)n * Cc + c) * Sp);
    const float4* ap = (const float4*)(g_attn + (size_t)n * Sp);

    float acc = 0.f;
#pragma unroll
    for (int i = 0; i < 8; i++) {
        float4 xv = __ldg(xp + tid + i * 128);
        float4 av = __ldg(ap + tid + i * 128);
        acc += xv.x * av.x + xv.y * av.y + xv.z * av.z + xv.w * av.w;
    }

    __shared__ float s[128];
    s[tid] = acc;
    __syncthreads();
#pragma unroll
    for (int off = 64; off >= 32; off >>= 1) {
        if (tid < off) s[tid] += s[tid + off];
        __syncthreads();
    }
    if (tid < 32) {
        float v = s[tid];
#pragma unroll
        for (int o = 16; o; o >>= 1) v += __shfl_xor_sync(0xffffffffu, v, o);
        if (tid == 0) g_ctx[(size_t)n * Cc + c] = v;
    }
}

// ---------------------------------------------------------------------------
// K4: tiny bottleneck MLP: v = ctx @ wv1^T ; LayerNorm over 32 ch ; ReLU ;
//     delta = v @ wv2^T.  One block, 1024 threads (warp per n for LN).
// ---------------------------------------------------------------------------
__global__ void k_mlp(const float* __restrict__ wv1,
                      const float* __restrict__ ln_g,
                      const float* __restrict__ ln_b,
                      const float* __restrict__ wv2) {
    int tid = threadIdx.x;            // 0..1023
    int n = tid >> 5;                 // warp index = batch
    int j = tid & 31;                 // bottleneck channel = lane

    const float* ctx = g_ctx + (size_t)n * Cc;
    const float* w1 = wv1 + (size_t)j * Cc;
    float acc = 0.f;
#pragma unroll 8
    for (int k = 0; k < Cc; k++) acc += ctx[k] * __ldg(&w1[k]);

    // LayerNorm across the 32 lanes of this warp
    float mu = acc;
#pragma unroll
    for (int o = 16; o; o >>= 1) mu += __shfl_xor_sync(0xffffffffu, mu, o);
    mu *= (1.f / 32.f);
    float d = acc - mu;
    float var = d * d;
#pragma unroll
    for (int o = 16; o; o >>= 1) var += __shfl_xor_sync(0xffffffffu, var, o);
    var *= (1.f / 32.f);
    float v = d * rsqrtf(var + EPSv) * __ldg(&ln_g[j]) + __ldg(&ln_b[j]);
    v = fmaxf(v, 0.f);

    __shared__ float sv[Nn][CBn];
    sv[n][j] = v;
    __syncthreads();

    for (int idx = tid; idx < Nn * Cc; idx += 1024) {
        int n2 = idx >> 9;
        int c = idx & 511;
        const float* w2 = wv2 + (size_t)c * CBn;
        float s = 0.f;
#pragma unroll
        for (int jj = 0; jj < CBn; jj++) s += sv[n2][jj] * __ldg(&w2[jj]);
        g_delta[idx] = s;
    }
}

// ---------------------------------------------------------------------------
// K5: out[n,c,h,w] = x[n,c,h,w] + delta[n,c]   (float4 streaming)
// ---------------------------------------------------------------------------
__global__ void k_add(const float* __restrict__ x, float* __restrict__ out) {
    size_t i = (size_t)blockIdx.x * blockDim.x + threadIdx.x;  // float4 index
    float4 v = __ldg((const float4*)x + i);
    int nc = (int)(i >> 10);          // (i*4)/4096
    float d = __ldg(&g_delta[nc]);
    float4 o = make_float4(v.x + d, v.y + d, v.z + d, v.w + d);
    ((float4*)out)[i] = o;
}

// ---------------------------------------------------------------------------
extern "C" void kernel_launch(void* const* d_in, const int* in_sizes, int n_in,
                              void* d_out, int out_size) {
    const float* x    = (const float*)d_in[0];
    const float* wk_w = (const float*)d_in[1];
    const float* wk_b = (const float*)d_in[2];
    const float* wv1  = (const float*)d_in[3];
    const float* ln_g = (const float*)d_in[4];
    const float* ln_b = (const float*)d_in[5];
    const float* wv2  = (const float*)d_in[6];
    float* out = (float*)d_out;

    k_logits<<<Nn * Hh, 256>>>(x, wk_w, wk_b);
    k_softmax<<<Nn, Ww>>>();
    k_ctx<<<Nn * Cc, 128>>>(x);
    k_mlp<<<1, 1024>>>(wv1, ln_g, ln_b, wv2);

    size_t total4 = (size_t)Nn * Cc * Sp / 4;   // 16M float4
    k_add<<<(unsigned)(total4 / 256), 256>>>(x, out);
}

// round 2
// speedup vs baseline: 2.1160x; 2.1160x over previous
#include <cuda_runtime.h>

#define Nn 32
#define Cc 512
#define Hh 64
#define Ww 64
#define CBn 32          // bottleneck channels C/R
#define Sp (Hh*Ww)      // 4096 spatial per channel
#define EPSv 1e-5f
#define GRP 8           // batch group size for L2 blocking (8 * 8MB = 64MB < 126MB L2)

// Scratch (allocation-free rule: __device__ globals)
__device__ float g_attn[Nn * Sp];      // logits -> attn (in place)
__device__ float g_ctx[Nn * Cc];       // pooled context
__device__ float g_delta[Nn * Cc];     // per-(n,c) broadcast add term

// ---------------------------------------------------------------------------
// K1: logits[n,h,w] = sum_c x[n,c,h,w] * wk_w[c] + wk_b      (group of GRP n)
// block = (n,h) row; 256 threads = 16 w-float4 groups x 16 c-chunks of 32
// ---------------------------------------------------------------------------
__global__ void k_logits(const float* __restrict__ x,
                         const float* __restrict__ wk_w,
                         const float* __restrict__ wk_b, int n0) {
    int n = n0 + (blockIdx.x >> 6);   // / Hh
    int h = blockIdx.x & 63;          // % Hh
    int tid = threadIdx.x;            // 0..255
    int wq = tid & 15;                // float4 index over w (w = wq*4)
    int cc = tid >> 4;                // c-chunk 0..15 (32 channels each)

    const float4* xp = (const float4*)(x + (((size_t)(n * Cc + cc * 32)) * Hh + h) * Ww) + wq;
    const size_t cstride4 = Sp / 4;   // float4 stride between channels = 1024

    float4 acc = make_float4(0.f, 0.f, 0.f, 0.f);
#pragma unroll
    for (int i = 0; i < 32; i++) {
        float wv = __ldg(&wk_w[cc * 32 + i]);
        float4 v = __ldg(xp + (size_t)i * cstride4);
        acc.x += v.x * wv; acc.y += v.y * wv;
        acc.z += v.z * wv; acc.w += v.w * wv;
    }

    __shared__ float sred[16][Ww];
    sred[cc][wq * 4 + 0] = acc.x;
    sred[cc][wq * 4 + 1] = acc.y;
    sred[cc][wq * 4 + 2] = acc.z;
    sred[cc][wq * 4 + 3] = acc.w;
    __syncthreads();

    if (tid < Ww) {
        float s = 0.f;
#pragma unroll
        for (int k = 0; k < 16; k++) s += sred[k][tid];
        g_attn[((size_t)n * Hh + h) * Ww + tid] = s + __ldg(&wk_b[0]);
    }
}

// ---------------------------------------------------------------------------
// K2: softmax over H (axis=1) for each (n, w), in place on g_attn.
// ---------------------------------------------------------------------------
__global__ void k_softmax(int n0) {
    int n = n0 + blockIdx.x;
    int w = threadIdx.x;              // 0..63
    float* L = g_attn + (size_t)n * Sp;

    float vals[Hh];
    float m = -1e30f;
#pragma unroll
    for (int h = 0; h < Hh; h++) {
        vals[h] = L[h * Ww + w];
        m = fmaxf(m, vals[h]);
    }
    float sum = 0.f;
#pragma unroll
    for (int h = 0; h < Hh; h++) {
        vals[h] = __expf(vals[h] - m);
        sum += vals[h];
    }
    float inv = 1.f / sum;
#pragma unroll
    for (int h = 0; h < Hh; h++) L[h * Ww + w] = vals[h] * inv;
}

// ---------------------------------------------------------------------------
// K3: ctx[n,c] = sum_{h,w} x[n,c,h,w] * attn[n,h,w]        (x hits L2)
// block per (n,c); 128 threads reduce 4096 contiguous floats (float4).
// ---------------------------------------------------------------------------
__global__ void k_ctx(const float* __restrict__ x, int n0) {
    int n = n0 + (blockIdx.x >> 9);   // / Cc
    int c = blockIdx.x & 511;         // % Cc
    int tid = threadIdx.x;            // 0..127

    const float4* xp = (const float4*)(x + ((size_t)n * Cc + c) * Sp);
    const float4* ap = (const float4*)(g_attn + (size_t)n * Sp);

    float acc = 0.f;
#pragma unroll
    for (int i = 0; i < 8; i++) {
        float4 xv = __ldg(xp + tid + i * 128);
        float4 av = __ldg(ap + tid + i * 128);
        acc += xv.x * av.x + xv.y * av.y + xv.z * av.z + xv.w * av.w;
    }

    __shared__ float s[128];
    s[tid] = acc;
    __syncthreads();
#pragma unroll
    for (int off = 64; off >= 32; off >>= 1) {
        if (tid < off) s[tid] += s[tid + off];
        __syncthreads();
    }
    if (tid < 32) {
        float v = s[tid];
#pragma unroll
        for (int o = 16; o; o >>= 1) v += __shfl_xor_sync(0xffffffffu, v, o);
        if (tid == 0) g_ctx[(size_t)n * Cc + c] = v;
    }
}

// ---------------------------------------------------------------------------
// K4: bottleneck MLP, one block per n, 1024 threads.
//   v_j = dot(ctx[n,:], wv1[j,:])  -- warp j, 16 elems/lane + shfl reduce
//   LayerNorm+ReLU over 32 v's     -- warp 0
//   delta[n,c] = dot(v, wv2[c,:])  -- threads 0..511
// ---------------------------------------------------------------------------
__global__ void k_mlp(const float* __restrict__ wv1,
                      const float* __restrict__ ln_g,
                      const float* __restrict__ ln_b,
                      const float* __restrict__ wv2, int n0) {
    int n = n0 + blockIdx.x;
    int tid = threadIdx.x;            // 0..1023
    int wid = tid >> 5;               // warp = bottleneck channel j
    int lane = tid & 31;

    __shared__ float sctx[Cc];
    __shared__ float sv[CBn];

    if (tid < Cc) sctx[tid] = g_ctx[(size_t)n * Cc + tid];
    __syncthreads();

    // v_j
    float acc = 0.f;
    const float* w1 = wv1 + (size_t)wid * Cc;
#pragma unroll
    for (int k = 0; k < Cc / 32; k++) {
        int idx = lane + k * 32;
        acc += sctx[idx] * __ldg(&w1[idx]);
    }
#pragma unroll
    for (int o = 16; o; o >>= 1) acc += __shfl_xor_sync(0xffffffffu, acc, o);
    if (lane == 0) sv[wid] = acc;
    __syncthreads();

    // LayerNorm + ReLU over 32 values (warp 0)
    if (wid == 0) {
        float v = sv[lane];
        float mu = v;
#pragma unroll
        for (int o = 16; o; o >>= 1) mu += __shfl_xor_sync(0xffffffffu, mu, o);
        mu *= (1.f / 32.f);
        float d = v - mu;
        float var = d * d;
#pragma unroll
        for (int o = 16; o; o >>= 1) var += __shfl_xor_sync(0xffffffffu, var, o);
        var *= (1.f / 32.f);
        v = d * rsqrtf(var + EPSv) * __ldg(&ln_g[lane]) + __ldg(&ln_b[lane]);
        sv[lane] = fmaxf(v, 0.f);
    }
    __syncthreads();

    // delta[n,c]
    if (tid < Cc) {
        const float* w2 = wv2 + (size_t)tid * CBn;
        float s = 0.f;
#pragma unroll
        for (int j = 0; j < CBn; j++) s += sv[j] * __ldg(&w2[j]);
        g_delta[(size_t)n * Cc + tid] = s;
    }
}

// ---------------------------------------------------------------------------
// K5: out[n,c,h,w] = x[n,c,h,w] + delta[n,c]   (x hits L2; write streams out)
// Launched per group; pointers pre-offset to the group base.
// ---------------------------------------------------------------------------
__global__ void k_add(const float* __restrict__ x, float* __restrict__ out,
                      const float* __restrict__ delta) {
    size_t i = (size_t)blockIdx.x * blockDim.x + threadIdx.x;  // float4 index
    float4 v = __ldg((const float4*)x + i);
    int nc = (int)(i >> 10);          // (i*4)/4096
    float d = __ldg(&delta[nc]);
    float4 o = make_float4(v.x + d, v.y + d, v.z + d, v.w + d);
    ((float4*)out)[i] = o;
}

// ---------------------------------------------------------------------------
extern "C" void kernel_launch(void* const* d_in, const int* in_sizes, int n_in,
                              void* d_out, int out_size) {
    const float* x    = (const float*)d_in[0];
    const float* wk_w = (const float*)d_in[1];
    const float* wk_b = (const float*)d_in[2];
    const float* wv1  = (const float*)d_in[3];
    const float* ln_g = (const float*)d_in[4];
    const float* ln_b = (const float*)d_in[5];
    const float* wv2  = (const float*)d_in[6];
    float* out = (float*)d_out;

    float* d_delta = nullptr;
    cudaGetSymbolAddress((void**)&d_delta, g_delta);

    const size_t grp_elems = (size_t)GRP * Cc * Sp;       // 16M floats
    const unsigned add_blocks = (unsigned)(grp_elems / 4 / 256);

    for (int n0 = 0; n0 < Nn; n0 += GRP) {
        size_t xoff = (size_t)n0 * Cc * Sp;
        k_logits<<<GRP * Hh, 256>>>(x, wk_w, wk_b, n0);
        k_softmax<<<GRP, Ww>>>(n0);
        k_ctx<<<GRP * Cc, 128>>>(x, n0);
        k_mlp<<<GRP, 1024>>>(wv1, ln_g, ln_b, wv2, n0);
        k_add<<<add_blocks, 256>>>(x + xoff, out + xoff, d_delta + (size_t)n0 * Cc);
    }
}